// round 2
// baseline (speedup 1.0000x reference)
#include <cuda_runtime.h>

// ---------------------------------------------------------------------------
// PointwiseConvNet3D_RNN: per-voxel 4-layer GRU (H=64, T=24, B=16384) + MLP.
// Thread-per-voxel, fp32 with fma.rn.f32x2 packing over the reduction dim.
// R1: single-buffer h state (read-before-write), bounded unrolling (I-cache).
// ---------------------------------------------------------------------------

#define ULL unsigned long long

#define NVOX   16384
#define TMAX   24
#define H      64
#define G3     192          // 3*H
#define NTHR   128
#define NBLK   128

// Inter-layer sequence scratch: [t][j2][voxel] as float2 (ULL), ~96 MB.
static __device__ ULL g_scratch[TMAX * (H/2) * NVOX];
// Selected (out[len-1] + out[len-4]) per voxel: [j2][voxel] float2, 4 MB.
static __device__ ULL g_sel[(H/2) * NVOX];

__device__ __forceinline__ void fma2(ULL& d, ULL a, ULL b) {
    // d.lo = a.lo*b.lo + d.lo ; d.hi = a.hi*b.hi + d.hi
    asm("fma.rn.f32x2 %0, %1, %2, %0;" : "+l"(d) : "l"(a), "l"(b));
}
__device__ __forceinline__ float f2lo(ULL v) { return __uint_as_float((unsigned)v); }
__device__ __forceinline__ float f2hi(ULL v) { return __uint_as_float((unsigned)(v >> 32)); }
__device__ __forceinline__ ULL fpack(float a, float b) {
    return (ULL)__float_as_uint(a) | ((ULL)__float_as_uint(b) << 32);
}
__device__ __forceinline__ float sigf(float x) {
    float e = __expf(-x);
    return __fdividef(1.0f, 1.0f + e);
}
__device__ __forceinline__ float tanhf_fast(float x) {
    float e = __expf(-2.0f * fabsf(x));
    float r = __fdividef(1.0f - e, 1.0f + e);
    return copysignf(r, x);
}

// Shared memory float-offset layout
#define SM_WIH  0            // 12288 floats (layer0: first 192 hold wih0)
#define SM_WHH  12288        // 12288 floats
#define SM_BIH  24576        // 192
#define SM_BHH  24768        // 192
#define SM_HULL 24960        // byte off 99840: 2 x 4096 ULL (GRU uses 1st; MLP both)
#define SMEM_BYTES (24960 * 4 + 2 * 4096 * 8)   // 165376

__global__ void __launch_bounds__(NTHR, 1)
pcn3d_rnn_kernel(const float* __restrict__ x,
                 const int*   __restrict__ lengths,
                 const float* __restrict__ scalef,
                 const float* __restrict__ biasp,
                 const float* __restrict__ wih0,
                 const float* __restrict__ whh0,
                 const float* __restrict__ bih0,
                 const float* __restrict__ bhh0,
                 const float* __restrict__ wih,
                 const float* __restrict__ whh,
                 const float* __restrict__ bih,
                 const float* __restrict__ bhh,
                 const float* __restrict__ bng,
                 const float* __restrict__ bnb,
                 const float* __restrict__ bnm,
                 const float* __restrict__ bnv,
                 const float* __restrict__ fcW,
                 const float* __restrict__ fcb,
                 const float* __restrict__ fcWout,
                 const float* __restrict__ fcbout,
                 float* __restrict__ out)
{
    extern __shared__ float smf[];
    float* sWih = smf + SM_WIH;
    float* sWhh = smf + SM_WHH;
    float* sBih = smf + SM_BIH;
    float* sBhh = smf + SM_BHH;
    ULL* sH  = (ULL*)(smf + SM_HULL);      // single h-state buffer [j2*NTHR+tid]
    ULL* sHB = sH + 4096;                  // used only by MLP head

    const int tid = threadIdx.x;
    const int gv  = blockIdx.x * NTHR + tid;
    const int n   = gv >> 12;          // D*Hd*W = 4096
    const int rem = gv & 4095;
    const int len = lengths[n];        // in [4, 24]; uniform within block
    const int lm1 = len - 1;
    const int lm4 = len - 4;

    const float sc0 = scalef[0], sc1 = scalef[1], sc2 = scalef[2];
    const float bp0 = biasp[0],  bp1 = biasp[1],  bp2 = biasp[2];

    ULL h2[H/2];

    // ======================= Layer 0 (input dim = 1) =======================
    for (int i = tid; i < G3; i += NTHR) {
        sWih[i] = wih0[i];       // wih0 is [192,1]
        sBih[i] = bih0[i];
        sBhh[i] = bhh0[i];
    }
    {
        const float4* src = (const float4*)whh0;
        float4* dst = (float4*)sWhh;
        for (int i = tid; i < 3072; i += NTHR) dst[i] = src[i];
    }
    __syncthreads();

#pragma unroll
    for (int j2 = 0; j2 < H/2; j2++) { h2[j2] = 0ULL; sH[j2 * NTHR + tid] = 0ULL; }

#pragma unroll 1
    for (int t = 0; t < len; t++) {
        const int tm = t % 3;
        const float scl = (tm == 0) ? sc0 : ((tm == 1) ? sc1 : sc2);
        const float bpl = (tm == 0) ? bp0 : ((tm == 1) ? bp1 : bp2);
        const float vt = x[(n * TMAX + t) * 4096 + rem] * scl + bpl;

#pragma unroll 1
        for (int c = 0; c < 16; c++) {
            const int k0 = c * 4;
            ULL rA[4] = {0,0,0,0}, zA[4] = {0,0,0,0}, hnA[4] = {0,0,0,0};
            const float* Ur = sWhh + k0 * H;
#pragma unroll
            for (int j = 0; j < H; j += 4) {
                const int j2 = j >> 1;
                ULL ha = h2[j2], hb = h2[j2 + 1];
#pragma unroll
                for (int k = 0; k < 4; k++) {
                    const float* ur = Ur + k * H + j;
                    ulonglong2 b0 = *(const ulonglong2*)(ur);
                    ulonglong2 b1 = *(const ulonglong2*)(ur + 64*64);
                    ulonglong2 b2 = *(const ulonglong2*)(ur + 128*64);
                    fma2(rA[k],  b0.x, ha); fma2(rA[k],  b0.y, hb);
                    fma2(zA[k],  b1.x, ha); fma2(zA[k],  b1.y, hb);
                    fma2(hnA[k], b2.x, ha); fma2(hnA[k], b2.y, hb);
                }
            }
            // read old h (this chunk's slots) BEFORE overwriting them
            ULL hp0 = sH[(k0 >> 1) * NTHR + tid];
            ULL hp1 = sH[((k0 >> 1) + 1) * NTHR + tid];
            float hold[4] = { f2lo(hp0), f2hi(hp0), f2lo(hp1), f2hi(hp1) };
            float hnew[4];
#pragma unroll
            for (int k = 0; k < 4; k++) {
                const int g = k0 + k;
                float rpre = f2lo(rA[k]) + f2hi(rA[k]) + sWih[g]       * vt + sBih[g]       + sBhh[g];
                float zpre = f2lo(zA[k]) + f2hi(zA[k]) + sWih[64 + g]  * vt + sBih[64 + g]  + sBhh[64 + g];
                float xnp  = sWih[128 + g] * vt + sBih[128 + g];
                float hnp  = f2lo(hnA[k]) + f2hi(hnA[k]) + sBhh[128 + g];
                float r = sigf(rpre), z = sigf(zpre);
                float nn = tanhf_fast(xnp + r * hnp);
                hnew[k] = nn + z * (hold[k] - nn);
            }
            ULL p0 = fpack(hnew[0], hnew[1]);
            ULL p1 = fpack(hnew[2], hnew[3]);
            sH[(k0 >> 1) * NTHR + tid]       = p0;
            sH[((k0 >> 1) + 1) * NTHR + tid] = p1;
            g_scratch[(t * (H/2) + (k0 >> 1)) * NVOX + gv]     = p0;
            g_scratch[(t * (H/2) + (k0 >> 1) + 1) * NVOX + gv] = p1;
        }
#pragma unroll
        for (int j2 = 0; j2 < H/2; j2++) h2[j2] = sH[j2 * NTHR + tid];
    }

    // ======================= Layers 1..3 (input dim = 64) ==================
#pragma unroll 1
    for (int l = 0; l < 3; l++) {
        __syncthreads();
        {
            const float4* srcA = (const float4*)(wih + l * 12288);
            const float4* srcB = (const float4*)(whh + l * 12288);
            float4* dA = (float4*)sWih;
            float4* dB = (float4*)sWhh;
            for (int i = tid; i < 3072; i += NTHR) { dA[i] = srcA[i]; dB[i] = srcB[i]; }
            for (int i = tid; i < G3; i += NTHR) {
                sBih[i] = bih[l * G3 + i];
                sBhh[i] = bhh[l * G3 + i];
            }
        }
        __syncthreads();

#pragma unroll
        for (int j2 = 0; j2 < H/2; j2++) { h2[j2] = 0ULL; sH[j2 * NTHR + tid] = 0ULL; }

        const bool lastL = (l == 2);

#pragma unroll 1
        for (int t = 0; t < len; t++) {
            ULL xv2[H/2];
#pragma unroll
            for (int j2 = 0; j2 < H/2; j2++)
                xv2[j2] = g_scratch[(t * (H/2) + j2) * NVOX + gv];

#pragma unroll 1
            for (int c = 0; c < 16; c++) {
                const int k0 = c * 4;
                ULL rA[4] = {0,0,0,0}, zA[4] = {0,0,0,0};
                ULL xnA[4] = {0,0,0,0}, hnA[4] = {0,0,0,0};
                const float* Wr = sWih + k0 * H;
                const float* Ur = sWhh + k0 * H;
#pragma unroll
                for (int j = 0; j < H; j += 4) {
                    const int j2 = j >> 1;
                    ULL xa = xv2[j2], xb = xv2[j2 + 1];
                    ULL ha = h2[j2],  hb = h2[j2 + 1];
#pragma unroll
                    for (int k = 0; k < 4; k++) {
                        const float* wr = Wr + k * H + j;
                        const float* ur = Ur + k * H + j;
                        ulonglong2 a0 = *(const ulonglong2*)(wr);
                        ulonglong2 a1 = *(const ulonglong2*)(wr + 64*64);
                        ulonglong2 a2 = *(const ulonglong2*)(wr + 128*64);
                        ulonglong2 b0 = *(const ulonglong2*)(ur);
                        ulonglong2 b1 = *(const ulonglong2*)(ur + 64*64);
                        ulonglong2 b2 = *(const ulonglong2*)(ur + 128*64);
                        fma2(rA[k],  a0.x, xa); fma2(rA[k],  a0.y, xb);
                        fma2(rA[k],  b0.x, ha); fma2(rA[k],  b0.y, hb);
                        fma2(zA[k],  a1.x, xa); fma2(zA[k],  a1.y, xb);
                        fma2(zA[k],  b1.x, ha); fma2(zA[k],  b1.y, hb);
                        fma2(xnA[k], a2.x, xa); fma2(xnA[k], a2.y, xb);
                        fma2(hnA[k], b2.x, ha); fma2(hnA[k], b2.y, hb);
                    }
                }
                ULL hp0 = sH[(k0 >> 1) * NTHR + tid];
                ULL hp1 = sH[((k0 >> 1) + 1) * NTHR + tid];
                float hold[4] = { f2lo(hp0), f2hi(hp0), f2lo(hp1), f2hi(hp1) };
                float hnew[4];
#pragma unroll
                for (int k = 0; k < 4; k++) {
                    const int g = k0 + k;
                    float rpre = f2lo(rA[k])  + f2hi(rA[k])  + sBih[g]      + sBhh[g];
                    float zpre = f2lo(zA[k])  + f2hi(zA[k])  + sBih[64 + g] + sBhh[64 + g];
                    float xnp  = f2lo(xnA[k]) + f2hi(xnA[k]) + sBih[128 + g];
                    float hnp  = f2lo(hnA[k]) + f2hi(hnA[k]) + sBhh[128 + g];
                    float r = sigf(rpre), z = sigf(zpre);
                    float nn = tanhf_fast(xnp + r * hnp);
                    hnew[k] = nn + z * (hold[k] - nn);
                }
                ULL p0 = fpack(hnew[0], hnew[1]);
                ULL p1 = fpack(hnew[2], hnew[3]);
                sH[(k0 >> 1) * NTHR + tid]       = p0;
                sH[((k0 >> 1) + 1) * NTHR + tid] = p1;
                if (!lastL) {
                    g_scratch[(t * (H/2) + (k0 >> 1)) * NVOX + gv]     = p0;
                    g_scratch[(t * (H/2) + (k0 >> 1) + 1) * NVOX + gv] = p1;
                } else {
                    const int si0 = (k0 >> 1) * NVOX + gv;
                    const int si1 = ((k0 >> 1) + 1) * NVOX + gv;
                    if (t == lm4) { g_sel[si0] = p0; g_sel[si1] = p1; }
                    if (t == lm1) {
                        ULL q0 = g_sel[si0], q1 = g_sel[si1];
                        g_sel[si0] = fpack(f2lo(q0) + hnew[0], f2hi(q0) + hnew[1]);
                        g_sel[si1] = fpack(f2lo(q1) + hnew[2], f2hi(q1) + hnew[3]);
                    }
                }
            }
#pragma unroll
            for (int j2 = 0; j2 < H/2; j2++) h2[j2] = sH[j2 * NTHR + tid];
        }
    }

    // ======================= MLP head ======================================
    __syncthreads();
    // Reuse sWih..sWhh region (24576 floats) for MLP params.
    float* sBnA = smf;                 // 384: gamma/sqrt(var+eps)
    float* sBnB = smf + 384;           // 384: beta - mean*A
    float* sFcW = smf + 768;           // 5*64*64 = 20480
    float* sFcB = sFcW + 20480;        // 320
    float* sWo  = sFcB + 320;          // 64
    for (int i = tid; i < 384; i += NTHR) {
        float a = bng[i] * rsqrtf(bnv[i] + 1e-5f);
        sBnA[i] = a;
        sBnB[i] = bnb[i] - bnm[i] * a;
    }
    {
        const float4* src = (const float4*)fcW;
        float4* dst = (float4*)sFcW;
        for (int i = tid; i < 5120; i += NTHR) dst[i] = src[i];
    }
    for (int i = tid; i < 320; i += NTHR) sFcB[i] = fcb[i];
    for (int i = tid; i < H;   i += NTHR) sWo[i]  = fcWout[i];
    __syncthreads();

    float* aA = (float*)sH;    // activations [j*128 + tid]
    float* aB = (float*)sHB;
#pragma unroll
    for (int j2 = 0; j2 < H/2; j2++) {
        ULL p = g_sel[j2 * NVOX + gv];
        aA[(2 * j2) * NTHR + tid]     = f2lo(p);
        aA[(2 * j2 + 1) * NTHR + tid] = f2hi(p);
    }
    float* cur = aA;
    float* nxt = aB;
#pragma unroll 1
    for (int i = 0; i < 5; i++) {
        // s = silu(bn_i(h))  (in place on this thread's slice)
#pragma unroll 8
        for (int j = 0; j < H; j++) {
            float v = sBnA[i * H + j] * cur[j * NTHR + tid] + sBnB[i * H + j];
            cur[j * NTHR + tid] = v * sigf(v);
        }
#pragma unroll 1
        for (int o = 0; o < H; o++) {
            float acc = sFcB[i * H + o];
            const float* wrow = sFcW + (i * H + o) * H;
#pragma unroll 16
            for (int j = 0; j < H; j++)
                acc += wrow[j] * cur[j * NTHR + tid];
            nxt[o * NTHR + tid] = acc;
        }
        float* tmp = cur; cur = nxt; nxt = tmp;
    }
    float acc = fcbout[0];
#pragma unroll 8
    for (int j = 0; j < H; j++) {
        float v = sBnA[5 * H + j] * cur[j * NTHR + tid] + sBnB[5 * H + j];
        acc += sWo[j] * (v * sigf(v));
    }
    out[gv] = acc;
}

extern "C" void kernel_launch(void* const* d_in, const int* in_sizes, int n_in,
                              void* d_out, int out_size)
{
    (void)in_sizes; (void)n_in; (void)out_size;
    const float* x      = (const float*)d_in[0];
    const int*   lens   = (const int*)  d_in[1];
    const float* scalef = (const float*)d_in[2];
    const float* biasp  = (const float*)d_in[3];
    const float* wih0   = (const float*)d_in[4];
    const float* whh0   = (const float*)d_in[5];
    const float* bih0   = (const float*)d_in[6];
    const float* bhh0   = (const float*)d_in[7];
    const float* wih    = (const float*)d_in[8];
    const float* whh    = (const float*)d_in[9];
    const float* bih    = (const float*)d_in[10];
    const float* bhh    = (const float*)d_in[11];
    const float* bng    = (const float*)d_in[12];
    const float* bnb    = (const float*)d_in[13];
    const float* bnm    = (const float*)d_in[14];
    const float* bnv    = (const float*)d_in[15];
    const float* fcW    = (const float*)d_in[16];
    const float* fcb    = (const float*)d_in[17];
    const float* fcWout = (const float*)d_in[18];
    const float* fcbout = (const float*)d_in[19];
    float* out = (float*)d_out;

    static int attr_set = 0;
    if (!attr_set) {
        cudaFuncSetAttribute(pcn3d_rnn_kernel,
                             cudaFuncAttributeMaxDynamicSharedMemorySize, SMEM_BYTES);
        attr_set = 1;
    }
    pcn3d_rnn_kernel<<<NBLK, NTHR, SMEM_BYTES>>>(
        x, lens, scalef, biasp, wih0, whh0, bih0, bhh0,
        wih, whh, bih, bhh, bng, bnb, bnm, bnv,
        fcW, fcb, fcWout, fcbout, out);
}

// round 5
// speedup vs baseline: 1.0108x; 1.0108x over previous
#include <cuda_runtime.h>

// ---------------------------------------------------------------------------
// PointwiseConvNet3D_RNN: per-voxel 4-layer GRU (H=64, T=24, B=16384) + MLP.
// R5 (= R4 resubmit): 2 threads per voxel (gate-split) -> 256 thr/block,
//     2 warps/SMSP. Ping-pong h-state -> single __syncthreads per timestep.
//     fp32 with fma.rn.f32x2 packing over the reduction dim.
// ---------------------------------------------------------------------------

#define ULL unsigned long long

#define NVOX   16384
#define TMAX   24
#define H      64
#define G3     192          // 3*H
#define VPB    128          // voxels per block
#define NTHR   256          // 2 threads per voxel
#define NBLK   128

// Inter-layer sequence scratch: [t][j2][voxel] as float2 (ULL), ~96 MB.
static __device__ ULL g_scratch[TMAX * (H/2) * NVOX];
// Selected (out[len-1] + out[len-4]) per voxel: [j2][voxel] float2, 4 MB.
static __device__ ULL g_sel[(H/2) * NVOX];

__device__ __forceinline__ void fma2(ULL& d, ULL a, ULL b) {
    asm("fma.rn.f32x2 %0, %1, %2, %0;" : "+l"(d) : "l"(a), "l"(b));
}
__device__ __forceinline__ float f2lo(ULL v) { return __uint_as_float((unsigned)v); }
__device__ __forceinline__ float f2hi(ULL v) { return __uint_as_float((unsigned)(v >> 32)); }
__device__ __forceinline__ ULL fpack(float a, float b) {
    return (ULL)__float_as_uint(a) | ((ULL)__float_as_uint(b) << 32);
}
__device__ __forceinline__ float sigf(float x) {
    float e = __expf(-x);
    return __fdividef(1.0f, 1.0f + e);
}
__device__ __forceinline__ float tanhf_fast(float x) {
    float e = __expf(-2.0f * fabsf(x));
    float r = __fdividef(1.0f - e, 1.0f + e);
    return copysignf(r, x);
}

// Shared memory float-offset layout
#define SM_WIH  0            // 12288 floats (layer0: first 192 hold wih0)
#define SM_WHH  12288        // 12288 floats
#define SM_BIH  24576        // 192
#define SM_BHH  24768        // 192
#define SM_HULL 24960        // 2 x 4096 ULL ping-pong (GRU h; MLP act)
#define SMEM_BYTES (24960 * 4 + 2 * 4096 * 8)   // 165376

__global__ void __launch_bounds__(NTHR, 1)
pcn3d_rnn_kernel(const float* __restrict__ x,
                 const int*   __restrict__ lengths,
                 const float* __restrict__ scalef,
                 const float* __restrict__ biasp,
                 const float* __restrict__ wih0,
                 const float* __restrict__ whh0,
                 const float* __restrict__ bih0,
                 const float* __restrict__ bhh0,
                 const float* __restrict__ wih,
                 const float* __restrict__ whh,
                 const float* __restrict__ bih,
                 const float* __restrict__ bhh,
                 const float* __restrict__ bng,
                 const float* __restrict__ bnb,
                 const float* __restrict__ bnm,
                 const float* __restrict__ bnv,
                 const float* __restrict__ fcW,
                 const float* __restrict__ fcb,
                 const float* __restrict__ fcWout,
                 const float* __restrict__ fcbout,
                 float* __restrict__ out)
{
    extern __shared__ float smf[];
    float* sWih = smf + SM_WIH;
    float* sWhh = smf + SM_WHH;
    float* sBih = smf + SM_BIH;
    float* sBhh = smf + SM_BHH;
    ULL* sHA = (ULL*)(smf + SM_HULL);      // h-state ping [j2][voxel]
    ULL* sHB = sHA + 4096;                 // h-state pong

    const int tid  = threadIdx.x;
    const int v    = tid & (VPB - 1);      // voxel within block
    const int half = tid >> 7;             // 0: gates 0-31, 1: gates 32-63
    const int gv   = blockIdx.x * VPB + v;
    const int n    = gv >> 12;             // D*Hd*W = 4096
    const int rem  = gv & 4095;
    const int len  = lengths[n];           // uniform within block
    const int lm1  = len - 1;
    const int lm4  = len - 4;

    const float sc0 = scalef[0], sc1 = scalef[1], sc2 = scalef[2];
    const float bp0 = biasp[0],  bp1 = biasp[1],  bp2 = biasp[2];

    ULL h2[H/2];

    // ======================= Layer 0 (input dim = 1) =======================
    for (int i = tid; i < G3; i += NTHR) {
        sWih[i] = wih0[i];       // wih0 is [192,1]
        sBih[i] = bih0[i];
        sBhh[i] = bhh0[i];
    }
    {
        const float4* src = (const float4*)whh0;
        float4* dst = (float4*)sWhh;
        for (int i = tid; i < 3072; i += NTHR) dst[i] = src[i];
    }
    for (int i = tid; i < 4096; i += NTHR) sHA[i] = 0ULL;
    __syncthreads();

#pragma unroll
    for (int j2 = 0; j2 < H/2; j2++) h2[j2] = 0ULL;

    ULL* pA = sHA;   // holds h(t-1): old-h reads
    ULL* pB = sHB;   // receives h(t)

#pragma unroll 1
    for (int t = 0; t < len; t++) {
        const int tm = t % 3;
        const float scl = (tm == 0) ? sc0 : ((tm == 1) ? sc1 : sc2);
        const float bpl = (tm == 0) ? bp0 : ((tm == 1) ? bp1 : bp2);
        const float vt = x[(n * TMAX + t) * 4096 + rem] * scl + bpl;

#pragma unroll 1
        for (int c = 0; c < 8; c++) {
            const int k0 = half * 32 + c * 4;
            ULL rA[4] = {0,0,0,0}, zA[4] = {0,0,0,0}, hnA[4] = {0,0,0,0};
            const float* Ur = sWhh + k0 * H;
#pragma unroll
            for (int j = 0; j < H; j += 4) {
                const int j2 = j >> 1;
                ULL ha = h2[j2], hb = h2[j2 + 1];
#pragma unroll
                for (int k = 0; k < 4; k++) {
                    const float* ur = Ur + k * H + j;
                    ulonglong2 b0 = *(const ulonglong2*)(ur);
                    ulonglong2 b1 = *(const ulonglong2*)(ur + 64*64);
                    ulonglong2 b2 = *(const ulonglong2*)(ur + 128*64);
                    fma2(rA[k],  b0.x, ha); fma2(rA[k],  b0.y, hb);
                    fma2(zA[k],  b1.x, ha); fma2(zA[k],  b1.y, hb);
                    fma2(hnA[k], b2.x, ha); fma2(hnA[k], b2.y, hb);
                }
            }
            // old h for this chunk from the ping buffer (not written this step)
            ULL hp0 = pA[(k0 >> 1) * VPB + v];
            ULL hp1 = pA[((k0 >> 1) + 1) * VPB + v];
            float hold[4] = { f2lo(hp0), f2hi(hp0), f2lo(hp1), f2hi(hp1) };
            float hnew[4];
#pragma unroll
            for (int k = 0; k < 4; k++) {
                const int g = k0 + k;
                float rpre = f2lo(rA[k]) + f2hi(rA[k]) + sWih[g]       * vt + sBih[g]       + sBhh[g];
                float zpre = f2lo(zA[k]) + f2hi(zA[k]) + sWih[64 + g]  * vt + sBih[64 + g]  + sBhh[64 + g];
                float xnp  = sWih[128 + g] * vt + sBih[128 + g];
                float hnp  = f2lo(hnA[k]) + f2hi(hnA[k]) + sBhh[128 + g];
                float r = sigf(rpre), z = sigf(zpre);
                float nn = tanhf_fast(xnp + r * hnp);
                hnew[k] = nn + z * (hold[k] - nn);
            }
            ULL p0 = fpack(hnew[0], hnew[1]);
            ULL p1 = fpack(hnew[2], hnew[3]);
            pB[(k0 >> 1) * VPB + v]       = p0;
            pB[((k0 >> 1) + 1) * VPB + v] = p1;
            g_scratch[(t * (H/2) + (k0 >> 1)) * NVOX + gv]     = p0;
            g_scratch[(t * (H/2) + (k0 >> 1) + 1) * NVOX + gv] = p1;
        }
        __syncthreads();                       // h(t) fully written
#pragma unroll
        for (int j2 = 0; j2 < H/2; j2++) h2[j2] = pB[j2 * VPB + v];
        ULL* tmp = pA; pA = pB; pB = tmp;      // next step writes other buffer
    }

    // ======================= Layers 1..3 (input dim = 64) ==================
#pragma unroll 1
    for (int l = 0; l < 3; l++) {
        __syncthreads();
        {
            const float4* srcA = (const float4*)(wih + l * 12288);
            const float4* srcB = (const float4*)(whh + l * 12288);
            float4* dA = (float4*)sWih;
            float4* dB = (float4*)sWhh;
            for (int i = tid; i < 3072; i += NTHR) { dA[i] = srcA[i]; dB[i] = srcB[i]; }
            for (int i = tid; i < G3; i += NTHR) {
                sBih[i] = bih[l * G3 + i];
                sBhh[i] = bhh[l * G3 + i];
            }
            for (int i = tid; i < 4096; i += NTHR) sHA[i] = 0ULL;
        }
        __syncthreads();

#pragma unroll
        for (int j2 = 0; j2 < H/2; j2++) h2[j2] = 0ULL;
        pA = sHA; pB = sHB;

        const bool lastL = (l == 2);

#pragma unroll 1
        for (int t = 0; t < len; t++) {
            ULL xv2[H/2];
#pragma unroll
            for (int j2 = 0; j2 < H/2; j2++)
                xv2[j2] = g_scratch[(t * (H/2) + j2) * NVOX + gv];

#pragma unroll 1
            for (int c = 0; c < 8; c++) {
                const int k0 = half * 32 + c * 4;
                ULL rA[4] = {0,0,0,0}, zA[4] = {0,0,0,0};
                ULL xnA[4] = {0,0,0,0}, hnA[4] = {0,0,0,0};
                const float* Wr = sWih + k0 * H;
                const float* Ur = sWhh + k0 * H;
#pragma unroll
                for (int j = 0; j < H; j += 4) {
                    const int j2 = j >> 1;
                    ULL xa = xv2[j2], xb = xv2[j2 + 1];
                    ULL ha = h2[j2],  hb = h2[j2 + 1];
#pragma unroll
                    for (int k = 0; k < 4; k++) {
                        const float* wr = Wr + k * H + j;
                        const float* ur = Ur + k * H + j;
                        ulonglong2 a0 = *(const ulonglong2*)(wr);
                        ulonglong2 a1 = *(const ulonglong2*)(wr + 64*64);
                        ulonglong2 a2 = *(const ulonglong2*)(wr + 128*64);
                        ulonglong2 b0 = *(const ulonglong2*)(ur);
                        ulonglong2 b1 = *(const ulonglong2*)(ur + 64*64);
                        ulonglong2 b2 = *(const ulonglong2*)(ur + 128*64);
                        fma2(rA[k],  a0.x, xa); fma2(rA[k],  a0.y, xb);
                        fma2(rA[k],  b0.x, ha); fma2(rA[k],  b0.y, hb);
                        fma2(zA[k],  a1.x, xa); fma2(zA[k],  a1.y, xb);
                        fma2(zA[k],  b1.x, ha); fma2(zA[k],  b1.y, hb);
                        fma2(xnA[k], a2.x, xa); fma2(xnA[k], a2.y, xb);
                        fma2(hnA[k], b2.x, ha); fma2(hnA[k], b2.y, hb);
                    }
                }
                ULL hp0 = pA[(k0 >> 1) * VPB + v];
                ULL hp1 = pA[((k0 >> 1) + 1) * VPB + v];
                float hold[4] = { f2lo(hp0), f2hi(hp0), f2lo(hp1), f2hi(hp1) };
                float hnew[4];
#pragma unroll
                for (int k = 0; k < 4; k++) {
                    const int g = k0 + k;
                    float rpre = f2lo(rA[k])  + f2hi(rA[k])  + sBih[g]      + sBhh[g];
                    float zpre = f2lo(zA[k])  + f2hi(zA[k])  + sBih[64 + g] + sBhh[64 + g];
                    float xnp  = f2lo(xnA[k]) + f2hi(xnA[k]) + sBih[128 + g];
                    float hnp  = f2lo(hnA[k]) + f2hi(hnA[k]) + sBhh[128 + g];
                    float r = sigf(rpre), z = sigf(zpre);
                    float nn = tanhf_fast(xnp + r * hnp);
                    hnew[k] = nn + z * (hold[k] - nn);
                }
                ULL p0 = fpack(hnew[0], hnew[1]);
                ULL p1 = fpack(hnew[2], hnew[3]);
                pB[(k0 >> 1) * VPB + v]       = p0;
                pB[((k0 >> 1) + 1) * VPB + v] = p1;
                if (!lastL) {
                    g_scratch[(t * (H/2) + (k0 >> 1)) * NVOX + gv]     = p0;
                    g_scratch[(t * (H/2) + (k0 >> 1) + 1) * NVOX + gv] = p1;
                } else {
                    const int si0 = (k0 >> 1) * NVOX + gv;
                    const int si1 = ((k0 >> 1) + 1) * NVOX + gv;
                    if (t == lm4) { g_sel[si0] = p0; g_sel[si1] = p1; }
                    if (t == lm1) {
                        ULL q0 = g_sel[si0], q1 = g_sel[si1];
                        g_sel[si0] = fpack(f2lo(q0) + hnew[0], f2hi(q0) + hnew[1]);
                        g_sel[si1] = fpack(f2lo(q1) + hnew[2], f2hi(q1) + hnew[3]);
                    }
                }
            }
            __syncthreads();
#pragma unroll
            for (int j2 = 0; j2 < H/2; j2++) h2[j2] = pB[j2 * VPB + v];
            ULL* tmp = pA; pA = pB; pB = tmp;
        }
    }

    // ======================= MLP head ======================================
    __syncthreads();
    // Reuse sWih..sWhh region (24576 floats) for MLP params.
    float* sBnA = smf;                 // 384: gamma/sqrt(var+eps)
    float* sBnB = smf + 384;           // 384: beta - mean*A
    float* sFcW = smf + 768;           // 5*64*64 = 20480
    float* sFcB = sFcW + 20480;        // 320
    float* sWo  = sFcB + 320;          // 64
    for (int i = tid; i < 384; i += NTHR) {
        float a = bng[i] * rsqrtf(bnv[i] + 1e-5f);
        sBnA[i] = a;
        sBnB[i] = bnb[i] - bnm[i] * a;
    }
    {
        const float4* src = (const float4*)fcW;
        float4* dst = (float4*)sFcW;
        for (int i = tid; i < 5120; i += NTHR) dst[i] = src[i];
    }
    for (int i = tid; i < 320; i += NTHR) sFcB[i] = fcb[i];
    for (int i = tid; i < H;   i += NTHR) sWo[i]  = fcWout[i];
    __syncthreads();

    float* aA = (float*)sHA;   // activations [j*VPB + v]
    float* aB = (float*)sHB;
    // each half stages its own 16 j2 slots
#pragma unroll
    for (int jj = 0; jj < 16; jj++) {
        const int j2 = half * 16 + jj;
        ULL p = g_sel[j2 * NVOX + gv];
        aA[(2 * j2) * VPB + v]     = f2lo(p);
        aA[(2 * j2 + 1) * VPB + v] = f2hi(p);
    }
    __syncthreads();
    float* cur = aA;
    float* nxt = aB;
#pragma unroll 1
    for (int i = 0; i < 5; i++) {
        // silu(bn_i(.)) in place, each half its own 32 rows
#pragma unroll 8
        for (int jj = 0; jj < 32; jj++) {
            const int j = half * 32 + jj;
            float val = sBnA[i * H + j] * cur[j * VPB + v] + sBnB[i * H + j];
            cur[j * VPB + v] = val * sigf(val);
        }
        __syncthreads();
        float cvals[H];
#pragma unroll
        for (int j = 0; j < H; j++) cvals[j] = cur[j * VPB + v];
#pragma unroll 1
        for (int oo = 0; oo < 32; oo++) {
            const int o = half * 32 + oo;
            float acc = sFcB[i * H + o];
            const float* wrow = sFcW + (i * H + o) * H;
#pragma unroll 16
            for (int j = 0; j < H; j++)
                acc += wrow[j] * cvals[j];
            nxt[o * VPB + v] = acc;
        }
        __syncthreads();
        float* tmp = cur; cur = nxt; nxt = tmp;
    }
    // final BN+silu + 64->1 projection
#pragma unroll 8
    for (int jj = 0; jj < 32; jj++) {
        const int j = half * 32 + jj;
        float val = sBnA[5 * H + j] * cur[j * VPB + v] + sBnB[5 * H + j];
        cur[j * VPB + v] = val * sigf(val);
    }
    __syncthreads();
    if (half == 0) {
        float acc = fcbout[0];
#pragma unroll 16
        for (int j = 0; j < H; j++)
            acc += sWo[j] * cur[j * VPB + v];
        out[gv] = acc;
    }
}

extern "C" void kernel_launch(void* const* d_in, const int* in_sizes, int n_in,
                              void* d_out, int out_size)
{
    (void)in_sizes; (void)n_in; (void)out_size;
    const float* x      = (const float*)d_in[0];
    const int*   lens   = (const int*)  d_in[1];
    const float* scalef = (const float*)d_in[2];
    const float* biasp  = (const float*)d_in[3];
    const float* wih0   = (const float*)d_in[4];
    const float* whh0   = (const float*)d_in[5];
    const float* bih0   = (const float*)d_in[6];
    const float* bhh0   = (const float*)d_in[7];
    const float* wih    = (const float*)d_in[8];
    const float* whh    = (const float*)d_in[9];
    const float* bih    = (const float*)d_in[10];
    const float* bhh    = (const float*)d_in[11];
    const float* bng    = (const float*)d_in[12];
    const float* bnb    = (const float*)d_in[13];
    const float* bnm    = (const float*)d_in[14];
    const float* bnv    = (const float*)d_in[15];
    const float* fcW    = (const float*)d_in[16];
    const float* fcb    = (const float*)d_in[17];
    const float* fcWout = (const float*)d_in[18];
    const float* fcbout = (const float*)d_in[19];
    float* out = (float*)d_out;

    cudaFuncSetAttribute(pcn3d_rnn_kernel,
                         cudaFuncAttributeMaxDynamicSharedMemorySize, SMEM_BYTES);
    pcn3d_rnn_kernel<<<NBLK, NTHR, SMEM_BYTES>>>(
        x, lens, scalef, biasp, wih0, whh0, bih0, bhh0,
        wih, whh, bih, bhh, bng, bnb, bnm, bnv,
        fcW, fcb, fcWout, fcbout, out);
}